// round 2
// baseline (speedup 1.0000x reference)
#include <cuda_runtime.h>
#include <math.h>

#define B_ 8
#define S_ 1024
#define E_ 1024
#define H_ 16
#define D_ 64
#define F_ 4096
#define TOK (B_ * S_)  // 8192

// ---------------- scratch (static device globals; no allocation) ----------------
__device__ float g_nx [(size_t)TOK * E_];
__device__ float g_q  [(size_t)TOK * E_];
__device__ float g_k  [(size_t)TOK * E_];
__device__ float g_v  [(size_t)TOK * E_];
__device__ float g_o  [(size_t)TOK * E_];
__device__ float g_x1 [(size_t)TOK * E_];
__device__ float g_nx2[(size_t)TOK * E_];
__device__ float g_h1 [(size_t)TOK * F_];

// ---------------- LayerNorm: one block per row of 1024 ----------------
__global__ __launch_bounds__(256) void ln_kernel(const float* __restrict__ x,
                                                 const float* __restrict__ g,
                                                 const float* __restrict__ be,
                                                 float* __restrict__ out)
{
    int row = blockIdx.x;
    int tid = threadIdx.x;
    const float4* xr = reinterpret_cast<const float4*>(x + (size_t)row * E_);
    float4 a = xr[tid];
    float s  = a.x + a.y + a.z + a.w;
    float ss = a.x * a.x + a.y * a.y + a.z * a.z + a.w * a.w;
#pragma unroll
    for (int o = 16; o > 0; o >>= 1) {
        s  += __shfl_xor_sync(0xffffffffu, s,  o);
        ss += __shfl_xor_sync(0xffffffffu, ss, o);
    }
    __shared__ float sm[8], sm2[8];
    int w = tid >> 5, lane = tid & 31;
    if (lane == 0) { sm[w] = s; sm2[w] = ss; }
    __syncthreads();
    if (tid < 32) {
        s  = (tid < 8) ? sm[tid]  : 0.f;
        ss = (tid < 8) ? sm2[tid] : 0.f;
#pragma unroll
        for (int o = 4; o > 0; o >>= 1) {
            s  += __shfl_xor_sync(0xffffffffu, s,  o);
            ss += __shfl_xor_sync(0xffffffffu, ss, o);
        }
        if (tid == 0) { sm[0] = s; sm2[0] = ss; }
    }
    __syncthreads();
    float mean = sm[0] * (1.0f / E_);
    float var  = sm2[0] * (1.0f / E_) - mean * mean;
    float inv  = rsqrtf(var + 1e-5f);
    float4 gg = reinterpret_cast<const float4*>(g)[tid];
    float4 bb = reinterpret_cast<const float4*>(be)[tid];
    float4 o4;
    o4.x = (a.x - mean) * inv * gg.x + bb.x;
    o4.y = (a.y - mean) * inv * gg.y + bb.y;
    o4.z = (a.z - mean) * inv * gg.z + bb.z;
    o4.w = (a.w - mean) * inv * gg.w + bb.w;
    reinterpret_cast<float4*>(out + (size_t)row * E_)[tid] = o4;
}

// ---------------- QKV projections: per (64-token tile, head, batch) ----------------
// q,k,v written in [B,H,S,D] layout for attention coalescing.
__global__ __launch_bounds__(256) void qkv_kernel(const float* __restrict__ nx,
                                                  const float* __restrict__ Wq,
                                                  const float* __restrict__ Wk,
                                                  const float* __restrict__ Wv,
                                                  float* __restrict__ q,
                                                  float* __restrict__ k,
                                                  float* __restrict__ v)
{
    int st = blockIdx.x, h = blockIdx.y, b = blockIdx.z;
    __shared__ float Xs[64][65];
    __shared__ float Ws[64][65];
    int tid = threadIdx.x;
    int tx = tid & 15, ty = tid >> 4;
    // load full 64x64 X tile: 1024 float4s, 256 threads -> 4 each
#pragma unroll
    for (int it = 0; it < 4; it++) {
        int idx = tid + it * 256;
        int r = idx >> 4, c4 = (idx & 15) * 4;
        const float* src = nx + ((size_t)(b * S_ + st * 64 + r)) * E_ + h * 64 + c4;
        float4 a = *reinterpret_cast<const float4*>(src);
        Xs[r][c4] = a.x; Xs[r][c4 + 1] = a.y; Xs[r][c4 + 2] = a.z; Xs[r][c4 + 3] = a.w;
    }
    const float* Wm[3] = {Wq, Wk, Wv};
    float*       Om[3] = {q, k, v};
    size_t obase = ((size_t)(b * H_ + h) * S_ + st * 64) * D_;
#pragma unroll 1
    for (int m = 0; m < 3; m++) {
        __syncthreads();
#pragma unroll
        for (int it = 0; it < 4; it++) {
            int idx = tid + it * 256;
            int r = idx >> 4, c4 = (idx & 15) * 4;
            float4 a = *reinterpret_cast<const float4*>(Wm[m] + r * 64 + c4);
            Ws[r][c4] = a.x; Ws[r][c4 + 1] = a.y; Ws[r][c4 + 2] = a.z; Ws[r][c4 + 3] = a.w;
        }
        __syncthreads();
        float acc[4][4] = {};
#pragma unroll 4
        for (int d = 0; d < 64; d++) {
            float av[4], bv[4];
#pragma unroll
            for (int i = 0; i < 4; i++) av[i] = Xs[ty * 4 + i][d];
#pragma unroll
            for (int j = 0; j < 4; j++) bv[j] = Ws[d][tx * 4 + j];
#pragma unroll
            for (int i = 0; i < 4; i++)
#pragma unroll
                for (int j = 0; j < 4; j++)
                    acc[i][j] = fmaf(av[i], bv[j], acc[i][j]);
        }
        float* dst = Om[m] + obase;
#pragma unroll
        for (int i = 0; i < 4; i++) {
            float4 o4 = {acc[i][0], acc[i][1], acc[i][2], acc[i][3]};
            *reinterpret_cast<float4*>(dst + (ty * 4 + i) * 64 + tx * 4) = o4;
        }
    }
}

// ---------------- Causal flash attention, 64x64 tiles ----------------
#define ATTN_SMEM_FLOATS (4096 + 64 * 65 + 4096 + 4096)
#define ATTN_SMEM_BYTES  (ATTN_SMEM_FLOATS * 4)

__global__ __launch_bounds__(256) void attn_kernel(const float* __restrict__ q,
                                                   const float* __restrict__ k,
                                                   const float* __restrict__ v,
                                                   float* __restrict__ o)
{
    extern __shared__ float smem[];
    float* Qs = smem;                 // [64][64]
    float* Ks = smem + 4096;          // [64][65] padded
    float* Vs = Ks + 64 * 65;         // [64][64]
    float* Ps = Vs + 4096;            // [64][64]
    __shared__ float m_s[64], l_s[64];

    int qt = blockIdx.x, h = blockIdx.y, b = blockIdx.z;
    int tid = threadIdx.x;
    int tx = tid & 15, ty = tid >> 4;
    const float scale = 0.03125f;  // 1/sqrt(E) = 1/32
    size_t head_base = (size_t)(b * H_ + h) * S_ * D_;

#pragma unroll
    for (int it = 0; it < 4; it++) {
        int idx = tid + it * 256;
        int r = idx >> 4, c4 = (idx & 15) * 4;
        float4 a = *reinterpret_cast<const float4*>(q + head_base + (size_t)(qt * 64 + r) * 64 + c4);
        Qs[r * 64 + c4]     = a.x * scale;
        Qs[r * 64 + c4 + 1] = a.y * scale;
        Qs[r * 64 + c4 + 2] = a.z * scale;
        Qs[r * 64 + c4 + 3] = a.w * scale;
    }
    if (tid < 64) { m_s[tid] = -1e30f; l_s[tid] = 0.f; }

    float acc[4][4] = {};

    for (int kt = 0; kt <= qt; kt++) {
        __syncthreads();  // protects Ks/Vs/Ps reuse + first-iter init
#pragma unroll
        for (int it = 0; it < 4; it++) {
            int idx = tid + it * 256;
            int r = idx >> 4, c4 = (idx & 15) * 4;
            float4 a = *reinterpret_cast<const float4*>(k + head_base + (size_t)(kt * 64 + r) * 64 + c4);
            Ks[r * 65 + c4] = a.x; Ks[r * 65 + c4 + 1] = a.y;
            Ks[r * 65 + c4 + 2] = a.z; Ks[r * 65 + c4 + 3] = a.w;
            float4 bb = *reinterpret_cast<const float4*>(v + head_base + (size_t)(kt * 64 + r) * 64 + c4);
            Vs[r * 64 + c4] = bb.x; Vs[r * 64 + c4 + 1] = bb.y;
            Vs[r * 64 + c4 + 2] = bb.z; Vs[r * 64 + c4 + 3] = bb.w;
        }
        __syncthreads();

        // S = (Q*scale) @ K^T  (4x4 micro-tile per thread)
        float s[4][4] = {};
#pragma unroll 4
        for (int d = 0; d < 64; d++) {
            float av[4], bv[4];
#pragma unroll
            for (int i = 0; i < 4; i++) av[i] = Qs[(ty * 4 + i) * 64 + d];
#pragma unroll
            for (int j = 0; j < 4; j++) bv[j] = Ks[(tx * 4 + j) * 65 + d];
#pragma unroll
            for (int i = 0; i < 4; i++)
#pragma unroll
                for (int j = 0; j < 4; j++)
                    s[i][j] = fmaf(av[i], bv[j], s[i][j]);
        }
        if (kt == qt) {
#pragma unroll
            for (int i = 0; i < 4; i++)
#pragma unroll
                for (int j = 0; j < 4; j++)
                    if (tx * 4 + j > ty * 4 + i) s[i][j] = -1e30f;
        }

        // online softmax: each 16-lane group owns rows ty*4..ty*4+3
#pragma unroll
        for (int i = 0; i < 4; i++) {
            int r = ty * 4 + i;
            float mm = fmaxf(fmaxf(s[i][0], s[i][1]), fmaxf(s[i][2], s[i][3]));
#pragma unroll
            for (int off = 8; off > 0; off >>= 1)
                mm = fmaxf(mm, __shfl_xor_sync(0xffffffffu, mm, off, 16));
            float mo = m_s[r];
            float mn = fmaxf(mo, mm);
            float corr = expf(mo - mn);
            float rs = 0.f;
#pragma unroll
            for (int j = 0; j < 4; j++) {
                float e = expf(s[i][j] - mn);
                Ps[r * 64 + tx * 4 + j] = e;
                rs += e;
            }
#pragma unroll
            for (int off = 8; off > 0; off >>= 1)
                rs += __shfl_xor_sync(0xffffffffu, rs, off, 16);
            if (tx == 0) { m_s[r] = mn; l_s[r] = l_s[r] * corr + rs; }
#pragma unroll
            for (int j = 0; j < 4; j++) acc[i][j] *= corr;
        }
        __syncthreads();

        // O += P @ V
#pragma unroll 4
        for (int kk = 0; kk < 64; kk++) {
            float pv[4], vv[4];
#pragma unroll
            for (int i = 0; i < 4; i++) pv[i] = Ps[(ty * 4 + i) * 64 + kk];
#pragma unroll
            for (int j = 0; j < 4; j++) vv[j] = Vs[kk * 64 + tx * 4 + j];
#pragma unroll
            for (int i = 0; i < 4; i++)
#pragma unroll
                for (int j = 0; j < 4; j++)
                    acc[i][j] = fmaf(pv[i], vv[j], acc[i][j]);
        }
    }

    // finalize; write o in token-major [B,S,H,D] = [TOK, E]
    float* ob = o + ((size_t)(b * S_ + qt * 64)) * E_ + h * 64;
#pragma unroll
    for (int i = 0; i < 4; i++) {
        float invl = 1.0f / l_s[ty * 4 + i];
        float4 o4 = {acc[i][0] * invl, acc[i][1] * invl, acc[i][2] * invl, acc[i][3] * invl};
        *reinterpret_cast<float4*>(ob + (size_t)(ty * 4 + i) * E_ + tx * 4) = o4;
    }
}

// ---------------- SGEMM 128x128x8, 8x8 per thread, fused epilogue ----------------
// C = A[M,K] @ B[K,N] + bias[N]  (+relu) (+resid[M,N])
template <int RELU, int RES>
__global__ __launch_bounds__(256) void gemm_kernel(const float* __restrict__ A,
                                                   const float* __restrict__ Bm,
                                                   const float* __restrict__ bias,
                                                   const float* __restrict__ resid,
                                                   float* __restrict__ C,
                                                   int M, int N, int K)
{
    __shared__ __align__(16) float As[8][128];
    __shared__ __align__(16) float Bs[8][128];
    int tid = threadIdx.x;
    int tx = tid & 15, ty = tid >> 4;
    int bx = blockIdx.x, by = blockIdx.y;
    const float* Ab = A + (size_t)by * 128 * K;
    const float* Bb = Bm + bx * 128;
    int arow = tid >> 1, acol = (tid & 1) * 4;
    int brow = tid >> 5, bcol = (tid & 31) * 4;
    float acc[8][8] = {};

    for (int k0 = 0; k0 < K; k0 += 8) {
        float4 a  = *reinterpret_cast<const float4*>(Ab + (size_t)arow * K + k0 + acol);
        float4 bv = *reinterpret_cast<const float4*>(Bb + (size_t)(k0 + brow) * N + bcol);
        __syncthreads();
        As[acol][arow] = a.x; As[acol + 1][arow] = a.y;
        As[acol + 2][arow] = a.z; As[acol + 3][arow] = a.w;
        *reinterpret_cast<float4*>(&Bs[brow][bcol]) = bv;
        __syncthreads();
#pragma unroll
        for (int kk = 0; kk < 8; kk++) {
            float av[8], bw[8];
            *reinterpret_cast<float4*>(av)     = *reinterpret_cast<const float4*>(&As[kk][ty * 8]);
            *reinterpret_cast<float4*>(av + 4) = *reinterpret_cast<const float4*>(&As[kk][ty * 8 + 4]);
            *reinterpret_cast<float4*>(bw)     = *reinterpret_cast<const float4*>(&Bs[kk][tx * 8]);
            *reinterpret_cast<float4*>(bw + 4) = *reinterpret_cast<const float4*>(&Bs[kk][tx * 8 + 4]);
#pragma unroll
            for (int i = 0; i < 8; i++)
#pragma unroll
                for (int j = 0; j < 8; j++)
                    acc[i][j] = fmaf(av[i], bw[j], acc[i][j]);
        }
    }

    int row0 = by * 128 + ty * 8;
    int col0 = bx * 128 + tx * 8;
    float bb[8];
#pragma unroll
    for (int j = 0; j < 8; j++) bb[j] = bias[col0 + j];
#pragma unroll
    for (int i = 0; i < 8; i++) {
        float* Cr = C + (size_t)(row0 + i) * N + col0;
        float vals[8];
#pragma unroll
        for (int j = 0; j < 8; j++) {
            float val = acc[i][j] + bb[j];
            if (RELU) val = fmaxf(val, 0.f);
            vals[j] = val;
        }
        if (RES) {
            const float* Rr = resid + (size_t)(row0 + i) * N + col0;
            float4 r0 = reinterpret_cast<const float4*>(Rr)[0];
            float4 r1 = reinterpret_cast<const float4*>(Rr)[1];
            vals[0] += r0.x; vals[1] += r0.y; vals[2] += r0.z; vals[3] += r0.w;
            vals[4] += r1.x; vals[5] += r1.y; vals[6] += r1.z; vals[7] += r1.w;
        }
        float4 o0 = {vals[0], vals[1], vals[2], vals[3]};
        float4 o1 = {vals[4], vals[5], vals[6], vals[7]};
        reinterpret_cast<float4*>(Cr)[0] = o0;
        reinterpret_cast<float4*>(Cr)[1] = o1;
    }
}

// ---------------- launch ----------------
extern "C" void kernel_launch(void* const* d_in, const int* in_sizes, int n_in,
                              void* d_out, int out_size)
{
    (void)in_sizes; (void)n_in; (void)out_size;
    const float* x   = (const float*)d_in[0];
    const float* Wq  = (const float*)d_in[1];
    const float* Wk  = (const float*)d_in[2];
    const float* Wv  = (const float*)d_in[3];
    const float* Wo  = (const float*)d_in[4];
    const float* bo  = (const float*)d_in[5];
    const float* W1  = (const float*)d_in[6];
    const float* b1  = (const float*)d_in[7];
    const float* W2  = (const float*)d_in[8];
    const float* b2  = (const float*)d_in[9];
    const float* g1  = (const float*)d_in[10];
    const float* be1 = (const float*)d_in[11];
    const float* g2  = (const float*)d_in[12];
    const float* be2 = (const float*)d_in[13];
    float* out = (float*)d_out;

    float *nx, *qb, *kb, *vb, *ob, *x1, *nx2, *h1;
    cudaGetSymbolAddress((void**)&nx,  g_nx);
    cudaGetSymbolAddress((void**)&qb,  g_q);
    cudaGetSymbolAddress((void**)&kb,  g_k);
    cudaGetSymbolAddress((void**)&vb,  g_v);
    cudaGetSymbolAddress((void**)&ob,  g_o);
    cudaGetSymbolAddress((void**)&x1,  g_x1);
    cudaGetSymbolAddress((void**)&nx2, g_nx2);
    cudaGetSymbolAddress((void**)&h1,  g_h1);

    cudaFuncSetAttribute(attn_kernel, cudaFuncAttributeMaxDynamicSharedMemorySize,
                         ATTN_SMEM_BYTES);

    // 1) LN1
    ln_kernel<<<TOK, 256>>>(x, g1, be1, nx);
    // 2) QKV projections
    qkv_kernel<<<dim3(S_ / 64, H_, B_), 256>>>(nx, Wq, Wk, Wv, qb, kb, vb);
    // 3) causal flash attention -> o (token-major)
    attn_kernel<<<dim3(S_ / 64, H_, B_), 256, ATTN_SMEM_BYTES>>>(qb, kb, vb, ob);
    // 4) x1 = x + o @ Wo + bo
    gemm_kernel<0, 1><<<dim3(E_ / 128, TOK / 128), 256>>>(ob, Wo, bo, x, x1, TOK, E_, E_);
    // 5) LN2
    ln_kernel<<<TOK, 256>>>(x1, g2, be2, nx2);
    // 6) h1 = relu(nx2 @ W1 + b1)
    gemm_kernel<1, 0><<<dim3(F_ / 128, TOK / 128), 256>>>(nx2, W1, b1, nullptr, h1, TOK, F_, E_);
    // 7) out = x1 + h1 @ W2 + b2
    gemm_kernel<0, 1><<<dim3(E_ / 128, TOK / 128), 256>>>(h1, W2, b2, x1, out, TOK, E_, F_);
}

// round 3
// speedup vs baseline: 2.1934x; 2.1934x over previous
#include <cuda_runtime.h>
#include <math.h>
#include <stdint.h>

#define B_ 8
#define S_ 1024
#define E_ 1024
#define H_ 16
#define D_ 64
#define F_ 4096
#define TOK (B_ * S_)  // 8192

// ---------------- scratch (static device globals; no allocation) ----------------
__device__ float g_nx [(size_t)TOK * E_];
__device__ float g_q  [(size_t)TOK * E_];
__device__ float g_k  [(size_t)TOK * E_];
__device__ float g_v  [(size_t)TOK * E_];
__device__ float g_o  [(size_t)TOK * E_];
__device__ float g_x1 [(size_t)TOK * E_];
__device__ float g_nx2[(size_t)TOK * E_];
__device__ float g_h1 [(size_t)TOK * F_];

// ---------------- helpers ----------------
__device__ __forceinline__ uint32_t f2tf32(float x) {
    uint32_t r;
    asm("cvt.rna.tf32.f32 %0, %1;" : "=r"(r) : "f"(x));
    return r;
}
__device__ __forceinline__ void cp_async16(void* smem, const void* gmem) {
    uint32_t s = (uint32_t)__cvta_generic_to_shared(smem);
    asm volatile("cp.async.cg.shared.global [%0], [%1], 16;\n" :: "r"(s), "l"(gmem));
}
#define CP_COMMIT() asm volatile("cp.async.commit_group;\n" ::: "memory")
#define CP_WAIT0()  asm volatile("cp.async.wait_group 0;\n" ::: "memory")

__device__ __forceinline__ void mma_tf32(float c[4], const uint32_t a[4], const uint32_t b[2]) {
    asm volatile(
        "mma.sync.aligned.m16n8k8.row.col.f32.tf32.tf32.f32 "
        "{%0,%1,%2,%3}, {%4,%5,%6,%7}, {%8,%9}, {%0,%1,%2,%3};\n"
        : "+f"(c[0]), "+f"(c[1]), "+f"(c[2]), "+f"(c[3])
        : "r"(a[0]), "r"(a[1]), "r"(a[2]), "r"(a[3]), "r"(b[0]), "r"(b[1]));
}

// ---------------- LayerNorm: one block per row of 1024 ----------------
__global__ __launch_bounds__(256) void ln_kernel(const float* __restrict__ x,
                                                 const float* __restrict__ g,
                                                 const float* __restrict__ be,
                                                 float* __restrict__ out)
{
    int row = blockIdx.x;
    int tid = threadIdx.x;
    const float4* xr = reinterpret_cast<const float4*>(x + (size_t)row * E_);
    float4 a = xr[tid];
    float s  = a.x + a.y + a.z + a.w;
    float ss = a.x * a.x + a.y * a.y + a.z * a.z + a.w * a.w;
#pragma unroll
    for (int o = 16; o > 0; o >>= 1) {
        s  += __shfl_xor_sync(0xffffffffu, s,  o);
        ss += __shfl_xor_sync(0xffffffffu, ss, o);
    }
    __shared__ float sm[8], sm2[8];
    int w = tid >> 5, lane = tid & 31;
    if (lane == 0) { sm[w] = s; sm2[w] = ss; }
    __syncthreads();
    if (tid < 32) {
        s  = (tid < 8) ? sm[tid]  : 0.f;
        ss = (tid < 8) ? sm2[tid] : 0.f;
#pragma unroll
        for (int o = 4; o > 0; o >>= 1) {
            s  += __shfl_xor_sync(0xffffffffu, s,  o);
            ss += __shfl_xor_sync(0xffffffffu, ss, o);
        }
        if (tid == 0) { sm[0] = s; sm2[0] = ss; }
    }
    __syncthreads();
    float mean = sm[0] * (1.0f / E_);
    float var  = sm2[0] * (1.0f / E_) - mean * mean;
    float inv  = rsqrtf(var + 1e-5f);
    float4 gg = reinterpret_cast<const float4*>(g)[tid];
    float4 bb = reinterpret_cast<const float4*>(be)[tid];
    float4 o4;
    o4.x = (a.x - mean) * inv * gg.x + bb.x;
    o4.y = (a.y - mean) * inv * gg.y + bb.y;
    o4.z = (a.z - mean) * inv * gg.z + bb.z;
    o4.w = (a.w - mean) * inv * gg.w + bb.w;
    reinterpret_cast<float4*>(out + (size_t)row * E_)[tid] = o4;
}

// ---------------- QKV projections: per (64-token tile, head, batch) ----------------
__global__ __launch_bounds__(256) void qkv_kernel(const float* __restrict__ nx,
                                                  const float* __restrict__ Wq,
                                                  const float* __restrict__ Wk,
                                                  const float* __restrict__ Wv,
                                                  float* __restrict__ q,
                                                  float* __restrict__ k,
                                                  float* __restrict__ v)
{
    int st = blockIdx.x, h = blockIdx.y, b = blockIdx.z;
    __shared__ float Xs[64][65];
    __shared__ float Ws[64][65];
    int tid = threadIdx.x;
    int tx = tid & 15, ty = tid >> 4;
#pragma unroll
    for (int it = 0; it < 4; it++) {
        int idx = tid + it * 256;
        int r = idx >> 4, c4 = (idx & 15) * 4;
        const float* src = nx + ((size_t)(b * S_ + st * 64 + r)) * E_ + h * 64 + c4;
        float4 a = *reinterpret_cast<const float4*>(src);
        Xs[r][c4] = a.x; Xs[r][c4 + 1] = a.y; Xs[r][c4 + 2] = a.z; Xs[r][c4 + 3] = a.w;
    }
    const float* Wm[3] = {Wq, Wk, Wv};
    float*       Om[3] = {q, k, v};
    size_t obase = ((size_t)(b * H_ + h) * S_ + st * 64) * D_;
#pragma unroll 1
    for (int m = 0; m < 3; m++) {
        __syncthreads();
#pragma unroll
        for (int it = 0; it < 4; it++) {
            int idx = tid + it * 256;
            int r = idx >> 4, c4 = (idx & 15) * 4;
            float4 a = *reinterpret_cast<const float4*>(Wm[m] + r * 64 + c4);
            Ws[r][c4] = a.x; Ws[r][c4 + 1] = a.y; Ws[r][c4 + 2] = a.z; Ws[r][c4 + 3] = a.w;
        }
        __syncthreads();
        float acc[4][4] = {};
#pragma unroll 4
        for (int d = 0; d < 64; d++) {
            float av[4], bv[4];
#pragma unroll
            for (int i = 0; i < 4; i++) av[i] = Xs[ty * 4 + i][d];
#pragma unroll
            for (int j = 0; j < 4; j++) bv[j] = Ws[d][tx * 4 + j];
#pragma unroll
            for (int i = 0; i < 4; i++)
#pragma unroll
                for (int j = 0; j < 4; j++)
                    acc[i][j] = fmaf(av[i], bv[j], acc[i][j]);
        }
        float* dst = Om[m] + obase;
#pragma unroll
        for (int i = 0; i < 4; i++) {
            float4 o4 = {acc[i][0], acc[i][1], acc[i][2], acc[i][3]};
            *reinterpret_cast<float4*>(dst + (ty * 4 + i) * 64 + tx * 4) = o4;
        }
    }
}

// ---------------- Causal flash attention, 64x64 tiles (fp32) ----------------
#define ATTN_SMEM_FLOATS (4096 + 64 * 65 + 4096 + 4096)
#define ATTN_SMEM_BYTES  (ATTN_SMEM_FLOATS * 4)

__global__ __launch_bounds__(256) void attn_kernel(const float* __restrict__ q,
                                                   const float* __restrict__ k,
                                                   const float* __restrict__ v,
                                                   float* __restrict__ o)
{
    extern __shared__ float smem[];
    float* Qs = smem;                 // [64][64]
    float* Ks = smem + 4096;          // [64][65] padded
    float* Vs = Ks + 64 * 65;         // [64][64]
    float* Ps = Vs + 4096;            // [64][64]
    __shared__ float m_s[64], l_s[64];

    int qt = blockIdx.x, h = blockIdx.y, b = blockIdx.z;
    int tid = threadIdx.x;
    int tx = tid & 15, ty = tid >> 4;
    const float scale = 0.03125f;  // 1/sqrt(E) = 1/32
    size_t head_base = (size_t)(b * H_ + h) * S_ * D_;

#pragma unroll
    for (int it = 0; it < 4; it++) {
        int idx = tid + it * 256;
        int r = idx >> 4, c4 = (idx & 15) * 4;
        float4 a = *reinterpret_cast<const float4*>(q + head_base + (size_t)(qt * 64 + r) * 64 + c4);
        Qs[r * 64 + c4]     = a.x * scale;
        Qs[r * 64 + c4 + 1] = a.y * scale;
        Qs[r * 64 + c4 + 2] = a.z * scale;
        Qs[r * 64 + c4 + 3] = a.w * scale;
    }
    if (tid < 64) { m_s[tid] = -1e30f; l_s[tid] = 0.f; }

    float acc[4][4] = {};

    for (int kt = 0; kt <= qt; kt++) {
        __syncthreads();
#pragma unroll
        for (int it = 0; it < 4; it++) {
            int idx = tid + it * 256;
            int r = idx >> 4, c4 = (idx & 15) * 4;
            float4 a = *reinterpret_cast<const float4*>(k + head_base + (size_t)(kt * 64 + r) * 64 + c4);
            Ks[r * 65 + c4] = a.x; Ks[r * 65 + c4 + 1] = a.y;
            Ks[r * 65 + c4 + 2] = a.z; Ks[r * 65 + c4 + 3] = a.w;
            float4 bb = *reinterpret_cast<const float4*>(v + head_base + (size_t)(kt * 64 + r) * 64 + c4);
            Vs[r * 64 + c4] = bb.x; Vs[r * 64 + c4 + 1] = bb.y;
            Vs[r * 64 + c4 + 2] = bb.z; Vs[r * 64 + c4 + 3] = bb.w;
        }
        __syncthreads();

        float s[4][4] = {};
#pragma unroll 4
        for (int d = 0; d < 64; d++) {
            float av[4], bv[4];
#pragma unroll
            for (int i = 0; i < 4; i++) av[i] = Qs[(ty * 4 + i) * 64 + d];
#pragma unroll
            for (int j = 0; j < 4; j++) bv[j] = Ks[(tx * 4 + j) * 65 + d];
#pragma unroll
            for (int i = 0; i < 4; i++)
#pragma unroll
                for (int j = 0; j < 4; j++)
                    s[i][j] = fmaf(av[i], bv[j], s[i][j]);
        }
        if (kt == qt) {
#pragma unroll
            for (int i = 0; i < 4; i++)
#pragma unroll
                for (int j = 0; j < 4; j++)
                    if (tx * 4 + j > ty * 4 + i) s[i][j] = -1e30f;
        }

#pragma unroll
        for (int i = 0; i < 4; i++) {
            int r = ty * 4 + i;
            float mm = fmaxf(fmaxf(s[i][0], s[i][1]), fmaxf(s[i][2], s[i][3]));
#pragma unroll
            for (int off = 8; off > 0; off >>= 1)
                mm = fmaxf(mm, __shfl_xor_sync(0xffffffffu, mm, off, 16));
            float mo = m_s[r];
            float mn = fmaxf(mo, mm);
            float corr = expf(mo - mn);
            float rs = 0.f;
#pragma unroll
            for (int j = 0; j < 4; j++) {
                float e = expf(s[i][j] - mn);
                Ps[r * 64 + tx * 4 + j] = e;
                rs += e;
            }
#pragma unroll
            for (int off = 8; off > 0; off >>= 1)
                rs += __shfl_xor_sync(0xffffffffu, rs, off, 16);
            if (tx == 0) { m_s[r] = mn; l_s[r] = l_s[r] * corr + rs; }
#pragma unroll
            for (int j = 0; j < 4; j++) acc[i][j] *= corr;
        }
        __syncthreads();

#pragma unroll 4
        for (int kk = 0; kk < 64; kk++) {
            float pv[4], vv[4];
#pragma unroll
            for (int i = 0; i < 4; i++) pv[i] = Ps[(ty * 4 + i) * 64 + kk];
#pragma unroll
            for (int j = 0; j < 4; j++) vv[j] = Vs[kk * 64 + tx * 4 + j];
#pragma unroll
            for (int i = 0; i < 4; i++)
#pragma unroll
                for (int j = 0; j < 4; j++)
                    acc[i][j] = fmaf(pv[i], vv[j], acc[i][j]);
        }
    }

    float* ob = o + ((size_t)(b * S_ + qt * 64)) * E_ + h * 64;
#pragma unroll
    for (int i = 0; i < 4; i++) {
        float invl = 1.0f / l_s[ty * 4 + i];
        float4 o4 = {acc[i][0] * invl, acc[i][1] * invl, acc[i][2] * invl, acc[i][3] * invl};
        *reinterpret_cast<float4*>(ob + (size_t)(ty * 4 + i) * E_ + tx * 4) = o4;
    }
}

// ---------------- TF32 tensor-core GEMM: 128x128x16 tiles, mma.m16n8k8 ----------------
// C = A[M,K] @ B[K,N] + bias[N]  (+relu) (+resid[M,N])
// 8 warps as 2(m) x 4(n); warp tile 64x32; double-buffered cp.async smem.
#define BM 128
#define BN 128
#define BK 16
#define APAD 4   // As row stride 20 -> fragment LDS conflict-free
#define BPAD 8   // Bs row stride 136 -> fragment LDS conflict-free

template <int RELU, int RES>
__global__ __launch_bounds__(256) void tgemm_kernel(const float* __restrict__ A,
                                                    const float* __restrict__ Bm,
                                                    const float* __restrict__ bias,
                                                    const float* __restrict__ resid,
                                                    float* __restrict__ C,
                                                    int M, int N, int K)
{
    __shared__ __align__(16) float As[2][BM][BK + APAD];
    __shared__ __align__(16) float Bs[2][BK][BN + BPAD];

    const int tid  = threadIdx.x;
    const int lane = tid & 31;
    const int warp = tid >> 5;
    const int wm = warp >> 2;          // 0..1
    const int wn = warp & 3;           // 0..3
    const int m_w = wm * 64;
    const int n_w = wn * 32;
    const int r4 = lane >> 2;          // 0..7
    const int c4 = lane & 3;           // 0..3
    const int bx = blockIdx.x, by = blockIdx.y;

    const float* Ab = A + (size_t)by * BM * K;
    const float* Bb = Bm + (size_t)bx * BN;

    // load-index decomposition (512 16B-chunks per tile each for A and B)
    const int a_row = (tid * 2) >> 2;          // rows: tid/2 (two chunks per thread, same... )
    // A: chunk idx = tid + i*256; row = idx>>2, kq = idx&3
    // B: chunk idx = tid + i*256; row = idx>>5, nq = idx&31

    auto load_tile = [&](int buf, int k0) {
#pragma unroll
        for (int i = 0; i < 2; i++) {
            int idx = tid + i * 256;
            int row = idx >> 2, kq = (idx & 3) * 4;
            cp_async16(&As[buf][row][kq], Ab + (size_t)row * K + k0 + kq);
        }
#pragma unroll
        for (int i = 0; i < 2; i++) {
            int idx = tid + i * 256;
            int row = idx >> 5, nq = (idx & 31) * 4;
            cp_async16(&Bs[buf][row][nq], Bb + (size_t)(k0 + row) * N + nq);
        }
        CP_COMMIT();
    };

    float acc[4][4][4] = {};

    load_tile(0, 0);
    const int nT = K / BK;
    int buf = 0;
#pragma unroll 1
    for (int t = 0; t < nT; t++) {
        CP_WAIT0();
        __syncthreads();
        if (t + 1 < nT) load_tile(buf ^ 1, (t + 1) * BK);

#pragma unroll
        for (int ks = 0; ks < 2; ks++) {
            const int kc = ks * 8;
            uint32_t a[4][4], b[4][2];
#pragma unroll
            for (int mi = 0; mi < 4; mi++) {
                int m0 = m_w + mi * 16;
                a[mi][0] = f2tf32(As[buf][m0 + r4][kc + c4]);
                a[mi][1] = f2tf32(As[buf][m0 + r4 + 8][kc + c4]);
                a[mi][2] = f2tf32(As[buf][m0 + r4][kc + c4 + 4]);
                a[mi][3] = f2tf32(As[buf][m0 + r4 + 8][kc + c4 + 4]);
            }
#pragma unroll
            for (int ni = 0; ni < 4; ni++) {
                int n0 = n_w + ni * 8;
                b[ni][0] = f2tf32(Bs[buf][kc + c4][n0 + r4]);
                b[ni][1] = f2tf32(Bs[buf][kc + c4 + 4][n0 + r4]);
            }
#pragma unroll
            for (int mi = 0; mi < 4; mi++)
#pragma unroll
                for (int ni = 0; ni < 4; ni++)
                    mma_tf32(acc[mi][ni], a[mi], b[ni]);
        }
        __syncthreads();
        buf ^= 1;
    }

    // epilogue
    const int row_base = by * BM + m_w;
    const int col_base = bx * BN + n_w;
#pragma unroll
    for (int mi = 0; mi < 4; mi++) {
#pragma unroll
        for (int ni = 0; ni < 4; ni++) {
            int c0 = col_base + ni * 8 + 2 * c4;
            float2 bb = *reinterpret_cast<const float2*>(bias + c0);
#pragma unroll
            for (int half = 0; half < 2; half++) {
                int r0 = row_base + mi * 16 + r4 + half * 8;
                float v0 = acc[mi][ni][half * 2]     + bb.x;
                float v1 = acc[mi][ni][half * 2 + 1] + bb.y;
                if (RELU) { v0 = fmaxf(v0, 0.f); v1 = fmaxf(v1, 0.f); }
                if (RES) {
                    float2 rr = *reinterpret_cast<const float2*>(resid + (size_t)r0 * N + c0);
                    v0 += rr.x; v1 += rr.y;
                }
                float2 o2 = {v0, v1};
                *reinterpret_cast<float2*>(C + (size_t)r0 * N + c0) = o2;
            }
        }
    }
}

// ---------------- launch ----------------
extern "C" void kernel_launch(void* const* d_in, const int* in_sizes, int n_in,
                              void* d_out, int out_size)
{
    (void)in_sizes; (void)n_in; (void)out_size;
    const float* x   = (const float*)d_in[0];
    const float* Wq  = (const float*)d_in[1];
    const float* Wk  = (const float*)d_in[2];
    const float* Wv  = (const float*)d_in[3];
    const float* Wo  = (const float*)d_in[4];
    const float* bo  = (const float*)d_in[5];
    const float* W1  = (const float*)d_in[6];
    const float* b1  = (const float*)d_in[7];
    const float* W2  = (const float*)d_in[8];
    const float* b2  = (const float*)d_in[9];
    const float* g1  = (const float*)d_in[10];
    const float* be1 = (const float*)d_in[11];
    const float* g2  = (const float*)d_in[12];
    const float* be2 = (const float*)d_in[13];
    float* out = (float*)d_out;

    float *nx, *qb, *kb, *vb, *ob, *x1, *nx2, *h1;
    cudaGetSymbolAddress((void**)&nx,  g_nx);
    cudaGetSymbolAddress((void**)&qb,  g_q);
    cudaGetSymbolAddress((void**)&kb,  g_k);
    cudaGetSymbolAddress((void**)&vb,  g_v);
    cudaGetSymbolAddress((void**)&ob,  g_o);
    cudaGetSymbolAddress((void**)&x1,  g_x1);
    cudaGetSymbolAddress((void**)&nx2, g_nx2);
    cudaGetSymbolAddress((void**)&h1,  g_h1);

    cudaFuncSetAttribute(attn_kernel, cudaFuncAttributeMaxDynamicSharedMemorySize,
                         ATTN_SMEM_BYTES);

    // 1) LN1
    ln_kernel<<<TOK, 256>>>(x, g1, be1, nx);
    // 2) QKV projections
    qkv_kernel<<<dim3(S_ / 64, H_, B_), 256>>>(nx, Wq, Wk, Wv, qb, kb, vb);
    // 3) causal flash attention -> o (token-major)
    attn_kernel<<<dim3(S_ / 64, H_, B_), 256, ATTN_SMEM_BYTES>>>(qb, kb, vb, ob);
    // 4) x1 = x + o @ Wo + bo   (tf32 tensor cores)
    tgemm_kernel<0, 1><<<dim3(E_ / BN, TOK / BM), 256>>>(ob, Wo, bo, x, x1, TOK, E_, E_);
    // 5) LN2
    ln_kernel<<<TOK, 256>>>(x1, g2, be2, nx2);
    // 6) h1 = relu(nx2 @ W1 + b1)
    tgemm_kernel<1, 0><<<dim3(F_ / BN, TOK / BM), 256>>>(nx2, W1, b1, nullptr, h1, TOK, F_, E_);
    // 7) out = x1 + h1 @ W2 + b2
    tgemm_kernel<0, 1><<<dim3(E_ / BN, TOK / BM), 256>>>(h1, W2, b2, x1, out, TOK, E_, F_);
}

// round 4
// speedup vs baseline: 2.2748x; 1.0371x over previous
#include <cuda_runtime.h>
#include <math.h>
#include <stdint.h>

#define B_ 8
#define S_ 1024
#define E_ 1024
#define H_ 16
#define D_ 64
#define F_ 4096
#define TOK (B_ * S_)  // 8192

// ---------------- scratch (static device globals; no allocation) ----------------
__device__ float g_nx [(size_t)TOK * E_];
__device__ float g_q  [(size_t)TOK * E_];
__device__ float g_k  [(size_t)TOK * E_];
__device__ float g_v  [(size_t)TOK * E_];
__device__ float g_o  [(size_t)TOK * E_];
__device__ float g_x1 [(size_t)TOK * E_];
__device__ float g_nx2[(size_t)TOK * E_];
__device__ float g_h1 [(size_t)TOK * F_];
__device__ float g_wo [(size_t)E_ * E_];
__device__ float g_w1 [(size_t)E_ * F_];
__device__ float g_w2 [(size_t)F_ * E_];

// ---------------- helpers ----------------
__device__ __forceinline__ uint32_t f2tf32(float x) {
    uint32_t r;
    asm("cvt.rna.tf32.f32 %0, %1;" : "=r"(r) : "f"(x));
    return r;
}
__device__ __forceinline__ float f2tf32f(float x) {
    return __uint_as_float(f2tf32(x));
}
__device__ __forceinline__ void cp_async16(void* smem, const void* gmem) {
    uint32_t s = (uint32_t)__cvta_generic_to_shared(smem);
    asm volatile("cp.async.cg.shared.global [%0], [%1], 16;\n" :: "r"(s), "l"(gmem));
}
#define CP_COMMIT() asm volatile("cp.async.commit_group;\n" ::: "memory")
#define CP_WAIT0()  asm volatile("cp.async.wait_group 0;\n" ::: "memory")
#define CP_WAIT1()  asm volatile("cp.async.wait_group 1;\n" ::: "memory")

__device__ __forceinline__ void mma_tf32(float c[4], const uint32_t a[4], const uint32_t b[2]) {
    asm volatile(
        "mma.sync.aligned.m16n8k8.row.col.f32.tf32.tf32.f32 "
        "{%0,%1,%2,%3}, {%4,%5,%6,%7}, {%8,%9}, {%0,%1,%2,%3};\n"
        : "+f"(c[0]), "+f"(c[1]), "+f"(c[2]), "+f"(c[3])
        : "r"(a[0]), "r"(a[1]), "r"(a[2]), "r"(a[3]), "r"(b[0]), "r"(b[1]));
}

// ---------------- weight pre-rounding to tf32 ----------------
__global__ __launch_bounds__(256) void cvt_tf32_kernel(const float* __restrict__ in,
                                                       float* __restrict__ out, int n4)
{
    int i = blockIdx.x * blockDim.x + threadIdx.x;
    if (i < n4) {
        float4 a = reinterpret_cast<const float4*>(in)[i];
        a.x = f2tf32f(a.x); a.y = f2tf32f(a.y); a.z = f2tf32f(a.z); a.w = f2tf32f(a.w);
        reinterpret_cast<float4*>(out)[i] = a;
    }
}

// ---------------- LayerNorm: one block per row of 1024 ----------------
template <int TF32OUT>
__global__ __launch_bounds__(256) void ln_kernel(const float* __restrict__ x,
                                                 const float* __restrict__ g,
                                                 const float* __restrict__ be,
                                                 float* __restrict__ out)
{
    int row = blockIdx.x;
    int tid = threadIdx.x;
    const float4* xr = reinterpret_cast<const float4*>(x + (size_t)row * E_);
    float4 a = xr[tid];
    float s  = a.x + a.y + a.z + a.w;
    float ss = a.x * a.x + a.y * a.y + a.z * a.z + a.w * a.w;
#pragma unroll
    for (int o = 16; o > 0; o >>= 1) {
        s  += __shfl_xor_sync(0xffffffffu, s,  o);
        ss += __shfl_xor_sync(0xffffffffu, ss, o);
    }
    __shared__ float sm[8], sm2[8];
    int w = tid >> 5, lane = tid & 31;
    if (lane == 0) { sm[w] = s; sm2[w] = ss; }
    __syncthreads();
    if (tid < 32) {
        s  = (tid < 8) ? sm[tid]  : 0.f;
        ss = (tid < 8) ? sm2[tid] : 0.f;
#pragma unroll
        for (int o = 4; o > 0; o >>= 1) {
            s  += __shfl_xor_sync(0xffffffffu, s,  o);
            ss += __shfl_xor_sync(0xffffffffu, ss, o);
        }
        if (tid == 0) { sm[0] = s; sm2[0] = ss; }
    }
    __syncthreads();
    float mean = sm[0] * (1.0f / E_);
    float var  = sm2[0] * (1.0f / E_) - mean * mean;
    float inv  = rsqrtf(var + 1e-5f);
    float4 gg = reinterpret_cast<const float4*>(g)[tid];
    float4 bb = reinterpret_cast<const float4*>(be)[tid];
    float4 o4;
    o4.x = (a.x - mean) * inv * gg.x + bb.x;
    o4.y = (a.y - mean) * inv * gg.y + bb.y;
    o4.z = (a.z - mean) * inv * gg.z + bb.z;
    o4.w = (a.w - mean) * inv * gg.w + bb.w;
    if (TF32OUT) {
        o4.x = f2tf32f(o4.x); o4.y = f2tf32f(o4.y);
        o4.z = f2tf32f(o4.z); o4.w = f2tf32f(o4.w);
    }
    reinterpret_cast<float4*>(out + (size_t)row * E_)[tid] = o4;
}

// ---------------- QKV projections: per (64-token tile, head, batch) ----------------
__global__ __launch_bounds__(256) void qkv_kernel(const float* __restrict__ nx,
                                                  const float* __restrict__ Wq,
                                                  const float* __restrict__ Wk,
                                                  const float* __restrict__ Wv,
                                                  float* __restrict__ q,
                                                  float* __restrict__ k,
                                                  float* __restrict__ v)
{
    int st = blockIdx.x, h = blockIdx.y, b = blockIdx.z;
    __shared__ float Xs[64][65];
    __shared__ float Ws[64][65];
    int tid = threadIdx.x;
    int tx = tid & 15, ty = tid >> 4;
#pragma unroll
    for (int it = 0; it < 4; it++) {
        int idx = tid + it * 256;
        int r = idx >> 4, c4 = (idx & 15) * 4;
        const float* src = nx + ((size_t)(b * S_ + st * 64 + r)) * E_ + h * 64 + c4;
        float4 a = *reinterpret_cast<const float4*>(src);
        Xs[r][c4] = a.x; Xs[r][c4 + 1] = a.y; Xs[r][c4 + 2] = a.z; Xs[r][c4 + 3] = a.w;
    }
    const float* Wm[3] = {Wq, Wk, Wv};
    float*       Om[3] = {q, k, v};
    size_t obase = ((size_t)(b * H_ + h) * S_ + st * 64) * D_;
#pragma unroll 1
    for (int m = 0; m < 3; m++) {
        __syncthreads();
#pragma unroll
        for (int it = 0; it < 4; it++) {
            int idx = tid + it * 256;
            int r = idx >> 4, c4 = (idx & 15) * 4;
            float4 a = *reinterpret_cast<const float4*>(Wm[m] + r * 64 + c4);
            Ws[r][c4] = a.x; Ws[r][c4 + 1] = a.y; Ws[r][c4 + 2] = a.z; Ws[r][c4 + 3] = a.w;
        }
        __syncthreads();
        float acc[4][4] = {};
#pragma unroll 4
        for (int d = 0; d < 64; d++) {
            float av[4], bv[4];
#pragma unroll
            for (int i = 0; i < 4; i++) av[i] = Xs[ty * 4 + i][d];
#pragma unroll
            for (int j = 0; j < 4; j++) bv[j] = Ws[d][tx * 4 + j];
#pragma unroll
            for (int i = 0; i < 4; i++)
#pragma unroll
                for (int j = 0; j < 4; j++)
                    acc[i][j] = fmaf(av[i], bv[j], acc[i][j]);
        }
        float* dst = Om[m] + obase;
#pragma unroll
        for (int i = 0; i < 4; i++) {
            float4 o4 = {acc[i][0], acc[i][1], acc[i][2], acc[i][3]};
            *reinterpret_cast<float4*>(dst + (ty * 4 + i) * 64 + tx * 4) = o4;
        }
    }
}

// ---------------- Causal flash attention, 64x64 tiles (fp32) ----------------
#define ATTN_SMEM_FLOATS (4096 + 64 * 65 + 4096 + 4096)
#define ATTN_SMEM_BYTES  (ATTN_SMEM_FLOATS * 4)

__global__ __launch_bounds__(256) void attn_kernel(const float* __restrict__ q,
                                                   const float* __restrict__ k,
                                                   const float* __restrict__ v,
                                                   float* __restrict__ o)
{
    extern __shared__ float smem[];
    float* Qs = smem;                 // [64][64]
    float* Ks = smem + 4096;          // [64][65] padded
    float* Vs = Ks + 64 * 65;         // [64][64]
    float* Ps = Vs + 4096;            // [64][64]
    __shared__ float m_s[64], l_s[64];

    int qt = blockIdx.x, h = blockIdx.y, b = blockIdx.z;
    int tid = threadIdx.x;
    int tx = tid & 15, ty = tid >> 4;
    const float scale = 0.03125f;  // 1/sqrt(E) = 1/32
    size_t head_base = (size_t)(b * H_ + h) * S_ * D_;

#pragma unroll
    for (int it = 0; it < 4; it++) {
        int idx = tid + it * 256;
        int r = idx >> 4, c4 = (idx & 15) * 4;
        float4 a = *reinterpret_cast<const float4*>(q + head_base + (size_t)(qt * 64 + r) * 64 + c4);
        Qs[r * 64 + c4]     = a.x * scale;
        Qs[r * 64 + c4 + 1] = a.y * scale;
        Qs[r * 64 + c4 + 2] = a.z * scale;
        Qs[r * 64 + c4 + 3] = a.w * scale;
    }
    if (tid < 64) { m_s[tid] = -1e30f; l_s[tid] = 0.f; }

    float acc[4][4] = {};

    for (int kt = 0; kt <= qt; kt++) {
        __syncthreads();
#pragma unroll
        for (int it = 0; it < 4; it++) {
            int idx = tid + it * 256;
            int r = idx >> 4, c4 = (idx & 15) * 4;
            float4 a = *reinterpret_cast<const float4*>(k + head_base + (size_t)(kt * 64 + r) * 64 + c4);
            Ks[r * 65 + c4] = a.x; Ks[r * 65 + c4 + 1] = a.y;
            Ks[r * 65 + c4 + 2] = a.z; Ks[r * 65 + c4 + 3] = a.w;
            float4 bb = *reinterpret_cast<const float4*>(v + head_base + (size_t)(kt * 64 + r) * 64 + c4);
            Vs[r * 64 + c4] = bb.x; Vs[r * 64 + c4 + 1] = bb.y;
            Vs[r * 64 + c4 + 2] = bb.z; Vs[r * 64 + c4 + 3] = bb.w;
        }
        __syncthreads();

        float s[4][4] = {};
#pragma unroll 4
        for (int d = 0; d < 64; d++) {
            float av[4], bv[4];
#pragma unroll
            for (int i = 0; i < 4; i++) av[i] = Qs[(ty * 4 + i) * 64 + d];
#pragma unroll
            for (int j = 0; j < 4; j++) bv[j] = Ks[(tx * 4 + j) * 65 + d];
#pragma unroll
            for (int i = 0; i < 4; i++)
#pragma unroll
                for (int j = 0; j < 4; j++)
                    s[i][j] = fmaf(av[i], bv[j], s[i][j]);
        }
        if (kt == qt) {
#pragma unroll
            for (int i = 0; i < 4; i++)
#pragma unroll
                for (int j = 0; j < 4; j++)
                    if (tx * 4 + j > ty * 4 + i) s[i][j] = -1e30f;
        }

#pragma unroll
        for (int i = 0; i < 4; i++) {
            int r = ty * 4 + i;
            float mm = fmaxf(fmaxf(s[i][0], s[i][1]), fmaxf(s[i][2], s[i][3]));
#pragma unroll
            for (int off = 8; off > 0; off >>= 1)
                mm = fmaxf(mm, __shfl_xor_sync(0xffffffffu, mm, off, 16));
            float mo = m_s[r];
            float mn = fmaxf(mo, mm);
            float corr = expf(mo - mn);
            float rs = 0.f;
#pragma unroll
            for (int j = 0; j < 4; j++) {
                float e = expf(s[i][j] - mn);
                Ps[r * 64 + tx * 4 + j] = e;
                rs += e;
            }
#pragma unroll
            for (int off = 8; off > 0; off >>= 1)
                rs += __shfl_xor_sync(0xffffffffu, rs, off, 16);
            if (tx == 0) { m_s[r] = mn; l_s[r] = l_s[r] * corr + rs; }
#pragma unroll
            for (int j = 0; j < 4; j++) acc[i][j] *= corr;
        }
        __syncthreads();

#pragma unroll 4
        for (int kk = 0; kk < 64; kk++) {
            float pv[4], vv[4];
#pragma unroll
            for (int i = 0; i < 4; i++) pv[i] = Ps[(ty * 4 + i) * 64 + kk];
#pragma unroll
            for (int j = 0; j < 4; j++) vv[j] = Vs[kk * 64 + tx * 4 + j];
#pragma unroll
            for (int i = 0; i < 4; i++)
#pragma unroll
                for (int j = 0; j < 4; j++)
                    acc[i][j] = fmaf(pv[i], vv[j], acc[i][j]);
        }
    }

    // finalize; write tf32-pre-rounded (consumed by Wo GEMM)
    float* ob = o + ((size_t)(b * S_ + qt * 64)) * E_ + h * 64;
#pragma unroll
    for (int i = 0; i < 4; i++) {
        float invl = 1.0f / l_s[ty * 4 + i];
        float4 o4 = {f2tf32f(acc[i][0] * invl), f2tf32f(acc[i][1] * invl),
                     f2tf32f(acc[i][2] * invl), f2tf32f(acc[i][3] * invl)};
        *reinterpret_cast<float4*>(ob + (size_t)(ty * 4 + i) * E_ + tx * 4) = o4;
    }
}

// ---------------- TF32 tensor-core GEMM: 128x128x16 tiles, 3-stage cp.async ----------------
// Inputs MUST be tf32-pre-rounded. C = A@B + bias (+relu) (+resid), optional tf32-rounded out.
#define BM 128
#define BN 128
#define BK 16
#define ASTRIDE 20        // BK + 4 pad
#define BSTRIDE 136       // BN + 8 pad
#define A_STAGE (BM * ASTRIDE)   // 2560 floats
#define B_STAGE (BK * BSTRIDE)   // 2176 floats
#define GEMM_SMEM_BYTES ((3 * A_STAGE + 3 * B_STAGE) * 4)  // 56832

template <int RELU, int RES, int TF32OUT>
__global__ __launch_bounds__(256) void tgemm_kernel(const float* __restrict__ A,
                                                    const float* __restrict__ Bm,
                                                    const float* __restrict__ bias,
                                                    const float* __restrict__ resid,
                                                    float* __restrict__ C,
                                                    int M, int N, int K)
{
    extern __shared__ float sh[];
    float* Asm = sh;                   // [3][BM][ASTRIDE]
    float* Bsm = sh + 3 * A_STAGE;     // [3][BK][BSTRIDE]

    const int tid  = threadIdx.x;
    const int lane = tid & 31;
    const int warp = tid >> 5;
    const int wm = warp >> 2;          // 0..1
    const int wn = warp & 3;           // 0..3
    const int m_w = wm * 64;
    const int n_w = wn * 32;
    const int r4 = lane >> 2;          // 0..7
    const int c4 = lane & 3;           // 0..3
    const int bx = blockIdx.x, by = blockIdx.y;

    const float* Ab = A + (size_t)by * BM * K;
    const float* Bb = Bm + (size_t)bx * BN;

    auto load_tile = [&](int buf, int k0) {
        float* Ad = Asm + buf * A_STAGE;
        float* Bd = Bsm + buf * B_STAGE;
#pragma unroll
        for (int i = 0; i < 2; i++) {
            int idx = tid + i * 256;
            int row = idx >> 2, kq = (idx & 3) * 4;
            cp_async16(Ad + row * ASTRIDE + kq, Ab + (size_t)row * K + k0 + kq);
        }
#pragma unroll
        for (int i = 0; i < 2; i++) {
            int idx = tid + i * 256;
            int row = idx >> 5, nq = (idx & 31) * 4;
            cp_async16(Bd + row * BSTRIDE + nq, Bb + (size_t)(k0 + row) * N + nq);
        }
        CP_COMMIT();
    };

    float acc[4][4][4] = {};

    const int nT = K / BK;
    load_tile(0, 0);
    load_tile(1, BK);

#pragma unroll 1
    for (int t = 0; t < nT; t++) {
        if (t + 1 < nT) { CP_WAIT1(); } else { CP_WAIT0(); }
        __syncthreads();
        if (t + 2 < nT) load_tile((t + 2) % 3, (t + 2) * BK);

        const float* Ac = Asm + (t % 3) * A_STAGE;
        const float* Bc = Bsm + (t % 3) * B_STAGE;
#pragma unroll
        for (int ks = 0; ks < 2; ks++) {
            const int kc = ks * 8;
            uint32_t a[4][4], b[4][2];
#pragma unroll
            for (int mi = 0; mi < 4; mi++) {
                int m0 = m_w + mi * 16;
                a[mi][0] = __float_as_uint(Ac[(m0 + r4) * ASTRIDE + kc + c4]);
                a[mi][1] = __float_as_uint(Ac[(m0 + r4 + 8) * ASTRIDE + kc + c4]);
                a[mi][2] = __float_as_uint(Ac[(m0 + r4) * ASTRIDE + kc + c4 + 4]);
                a[mi][3] = __float_as_uint(Ac[(m0 + r4 + 8) * ASTRIDE + kc + c4 + 4]);
            }
#pragma unroll
            for (int ni = 0; ni < 4; ni++) {
                int n0 = n_w + ni * 8;
                b[ni][0] = __float_as_uint(Bc[(kc + c4) * BSTRIDE + n0 + r4]);
                b[ni][1] = __float_as_uint(Bc[(kc + c4 + 4) * BSTRIDE + n0 + r4]);
            }
#pragma unroll
            for (int mi = 0; mi < 4; mi++)
#pragma unroll
                for (int ni = 0; ni < 4; ni++)
                    mma_tf32(acc[mi][ni], a[mi], b[ni]);
        }
        __syncthreads();
    }

    // epilogue
    const int row_base = by * BM + m_w;
    const int col_base = bx * BN + n_w;
#pragma unroll
    for (int mi = 0; mi < 4; mi++) {
#pragma unroll
        for (int ni = 0; ni < 4; ni++) {
            int c0 = col_base + ni * 8 + 2 * c4;
            float2 bb = *reinterpret_cast<const float2*>(bias + c0);
#pragma unroll
            for (int half = 0; half < 2; half++) {
                int r0 = row_base + mi * 16 + r4 + half * 8;
                float v0 = acc[mi][ni][half * 2]     + bb.x;
                float v1 = acc[mi][ni][half * 2 + 1] + bb.y;
                if (RELU) { v0 = fmaxf(v0, 0.f); v1 = fmaxf(v1, 0.f); }
                if (RES) {
                    float2 rr = *reinterpret_cast<const float2*>(resid + (size_t)r0 * N + c0);
                    v0 += rr.x; v1 += rr.y;
                }
                if (TF32OUT) { v0 = f2tf32f(v0); v1 = f2tf32f(v1); }
                float2 o2 = {v0, v1};
                *reinterpret_cast<float2*>(C + (size_t)r0 * N + c0) = o2;
            }
        }
    }
}

// ---------------- launch ----------------
extern "C" void kernel_launch(void* const* d_in, const int* in_sizes, int n_in,
                              void* d_out, int out_size)
{
    (void)in_sizes; (void)n_in; (void)out_size;
    const float* x   = (const float*)d_in[0];
    const float* Wq  = (const float*)d_in[1];
    const float* Wk  = (const float*)d_in[2];
    const float* Wv  = (const float*)d_in[3];
    const float* Wo  = (const float*)d_in[4];
    const float* bo  = (const float*)d_in[5];
    const float* W1  = (const float*)d_in[6];
    const float* b1  = (const float*)d_in[7];
    const float* W2  = (const float*)d_in[8];
    const float* b2  = (const float*)d_in[9];
    const float* g1  = (const float*)d_in[10];
    const float* be1 = (const float*)d_in[11];
    const float* g2  = (const float*)d_in[12];
    const float* be2 = (const float*)d_in[13];
    float* out = (float*)d_out;

    float *nx, *qb, *kb, *vb, *ob, *x1, *nx2, *h1, *wo, *w1, *w2;
    cudaGetSymbolAddress((void**)&nx,  g_nx);
    cudaGetSymbolAddress((void**)&qb,  g_q);
    cudaGetSymbolAddress((void**)&kb,  g_k);
    cudaGetSymbolAddress((void**)&vb,  g_v);
    cudaGetSymbolAddress((void**)&ob,  g_o);
    cudaGetSymbolAddress((void**)&x1,  g_x1);
    cudaGetSymbolAddress((void**)&nx2, g_nx2);
    cudaGetSymbolAddress((void**)&h1,  g_h1);
    cudaGetSymbolAddress((void**)&wo,  g_wo);
    cudaGetSymbolAddress((void**)&w1,  g_w1);
    cudaGetSymbolAddress((void**)&w2,  g_w2);

    cudaFuncSetAttribute(attn_kernel, cudaFuncAttributeMaxDynamicSharedMemorySize,
                         ATTN_SMEM_BYTES);
    cudaFuncSetAttribute(tgemm_kernel<0, 1, 0>, cudaFuncAttributeMaxDynamicSharedMemorySize,
                         GEMM_SMEM_BYTES);
    cudaFuncSetAttribute(tgemm_kernel<1, 0, 1>, cudaFuncAttributeMaxDynamicSharedMemorySize,
                         GEMM_SMEM_BYTES);

    // 0) pre-round weights to tf32
    cvt_tf32_kernel<<<(E_ * E_ / 4 + 255) / 256, 256>>>(Wo, wo, E_ * E_ / 4);
    cvt_tf32_kernel<<<(E_ * F_ / 4 + 255) / 256, 256>>>(W1, w1, E_ * F_ / 4);
    cvt_tf32_kernel<<<(F_ * E_ / 4 + 255) / 256, 256>>>(W2, w2, F_ * E_ / 4);
    // 1) LN1 (fp32 out: feeds fp32 QKV kernel)
    ln_kernel<0><<<TOK, 256>>>(x, g1, be1, nx);
    // 2) QKV projections
    qkv_kernel<<<dim3(S_ / 64, H_, B_), 256>>>(nx, Wq, Wk, Wv, qb, kb, vb);
    // 3) causal flash attention -> o (token-major, tf32-rounded)
    attn_kernel<<<dim3(S_ / 64, H_, B_), 256, ATTN_SMEM_BYTES>>>(qb, kb, vb, ob);
    // 4) x1 = x + o @ Wo + bo
    tgemm_kernel<0, 1, 0><<<dim3(E_ / BN, TOK / BM), 256, GEMM_SMEM_BYTES>>>(ob, wo, bo, x, x1, TOK, E_, E_);
    // 5) LN2 (tf32-rounded out)
    ln_kernel<1><<<TOK, 256>>>(x1, g2, be2, nx2);
    // 6) h1 = relu(nx2 @ W1 + b1), tf32-rounded out
    tgemm_kernel<1, 0, 1><<<dim3(F_ / BN, TOK / BM), 256, GEMM_SMEM_BYTES>>>(nx2, w1, b1, nullptr, h1, TOK, F_, E_);
    // 7) out = x1 + h1 @ W2 + b2
    tgemm_kernel<0, 1, 0><<<dim3(E_ / BN, TOK / BM), 256, GEMM_SMEM_BYTES>>>(h1, w2, b2, x1, out, TOK, E_, F_);
}

// round 5
// speedup vs baseline: 2.7874x; 1.2253x over previous
#include <cuda_runtime.h>
#include <math.h>
#include <stdint.h>

#define B_ 8
#define S_ 1024
#define E_ 1024
#define H_ 16
#define D_ 64
#define F_ 4096
#define TOK (B_ * S_)  // 8192

// ---------------- scratch (static device globals; no allocation) ----------------
__device__ float g_nx [(size_t)TOK * E_];
__device__ float g_q  [(size_t)TOK * E_];
__device__ float g_k  [(size_t)TOK * E_];
__device__ float g_v  [(size_t)TOK * E_];
__device__ float g_o  [(size_t)TOK * E_];
__device__ float g_x1 [(size_t)TOK * E_];
__device__ float g_nx2[(size_t)TOK * E_];
__device__ float g_h1 [(size_t)TOK * F_];
__device__ float g_wo [(size_t)E_ * E_];
__device__ float g_w1 [(size_t)E_ * F_];
__device__ float g_w2 [(size_t)F_ * E_];

// ---------------- helpers ----------------
__device__ __forceinline__ uint32_t f2tf32(float x) {
    uint32_t r;
    asm("cvt.rna.tf32.f32 %0, %1;" : "=r"(r) : "f"(x));
    return r;
}
__device__ __forceinline__ float f2tf32f(float x) {
    return __uint_as_float(f2tf32(x));
}
__device__ __forceinline__ void cp_async16(void* smem, const void* gmem) {
    uint32_t s = (uint32_t)__cvta_generic_to_shared(smem);
    asm volatile("cp.async.cg.shared.global [%0], [%1], 16;\n" :: "r"(s), "l"(gmem));
}
#define CP_COMMIT() asm volatile("cp.async.commit_group;\n" ::: "memory")
#define CP_WAIT0()  asm volatile("cp.async.wait_group 0;\n" ::: "memory")
#define CP_WAIT1()  asm volatile("cp.async.wait_group 1;\n" ::: "memory")

__device__ __forceinline__ void mma_tf32(float c[4], const uint32_t a[4], const uint32_t b[2]) {
    asm volatile(
        "mma.sync.aligned.m16n8k8.row.col.f32.tf32.tf32.f32 "
        "{%0,%1,%2,%3}, {%4,%5,%6,%7}, {%8,%9}, {%0,%1,%2,%3};\n"
        : "+f"(c[0]), "+f"(c[1]), "+f"(c[2]), "+f"(c[3])
        : "r"(a[0]), "r"(a[1]), "r"(a[2]), "r"(a[3]), "r"(b[0]), "r"(b[1]));
}

// ---------------- weight pre-rounding to tf32 ----------------
__global__ __launch_bounds__(256) void cvt_tf32_kernel(const float* __restrict__ in,
                                                       float* __restrict__ out, int n4)
{
    int i = blockIdx.x * blockDim.x + threadIdx.x;
    if (i < n4) {
        float4 a = reinterpret_cast<const float4*>(in)[i];
        a.x = f2tf32f(a.x); a.y = f2tf32f(a.y); a.z = f2tf32f(a.z); a.w = f2tf32f(a.w);
        reinterpret_cast<float4*>(out)[i] = a;
    }
}

// ---------------- LayerNorm: one block per row of 1024 ----------------
template <int TF32OUT>
__global__ __launch_bounds__(256) void ln_kernel(const float* __restrict__ x,
                                                 const float* __restrict__ g,
                                                 const float* __restrict__ be,
                                                 float* __restrict__ out)
{
    int row = blockIdx.x;
    int tid = threadIdx.x;
    const float4* xr = reinterpret_cast<const float4*>(x + (size_t)row * E_);
    float4 a = xr[tid];
    float s  = a.x + a.y + a.z + a.w;
    float ss = a.x * a.x + a.y * a.y + a.z * a.z + a.w * a.w;
#pragma unroll
    for (int o = 16; o > 0; o >>= 1) {
        s  += __shfl_xor_sync(0xffffffffu, s,  o);
        ss += __shfl_xor_sync(0xffffffffu, ss, o);
    }
    __shared__ float sm[8], sm2[8];
    int w = tid >> 5, lane = tid & 31;
    if (lane == 0) { sm[w] = s; sm2[w] = ss; }
    __syncthreads();
    if (tid < 32) {
        s  = (tid < 8) ? sm[tid]  : 0.f;
        ss = (tid < 8) ? sm2[tid] : 0.f;
#pragma unroll
        for (int o = 4; o > 0; o >>= 1) {
            s  += __shfl_xor_sync(0xffffffffu, s,  o);
            ss += __shfl_xor_sync(0xffffffffu, ss, o);
        }
        if (tid == 0) { sm[0] = s; sm2[0] = ss; }
    }
    __syncthreads();
    float mean = sm[0] * (1.0f / E_);
    float var  = sm2[0] * (1.0f / E_) - mean * mean;
    float inv  = rsqrtf(var + 1e-5f);
    float4 gg = reinterpret_cast<const float4*>(g)[tid];
    float4 bb = reinterpret_cast<const float4*>(be)[tid];
    float4 o4;
    o4.x = (a.x - mean) * inv * gg.x + bb.x;
    o4.y = (a.y - mean) * inv * gg.y + bb.y;
    o4.z = (a.z - mean) * inv * gg.z + bb.z;
    o4.w = (a.w - mean) * inv * gg.w + bb.w;
    if (TF32OUT) {
        o4.x = f2tf32f(o4.x); o4.y = f2tf32f(o4.y);
        o4.z = f2tf32f(o4.z); o4.w = f2tf32f(o4.w);
    }
    reinterpret_cast<float4*>(out + (size_t)row * E_)[tid] = o4;
}

// ---------------- QKV projections: per (64-token tile, head, batch) ----------------
__global__ __launch_bounds__(256) void qkv_kernel(const float* __restrict__ nx,
                                                  const float* __restrict__ Wq,
                                                  const float* __restrict__ Wk,
                                                  const float* __restrict__ Wv,
                                                  float* __restrict__ q,
                                                  float* __restrict__ k,
                                                  float* __restrict__ v)
{
    int st = blockIdx.x, h = blockIdx.y, b = blockIdx.z;
    __shared__ float Xs[64][65];
    __shared__ float Ws[64][65];
    int tid = threadIdx.x;
    int tx = tid & 15, ty = tid >> 4;
#pragma unroll
    for (int it = 0; it < 4; it++) {
        int idx = tid + it * 256;
        int r = idx >> 4, c4 = (idx & 15) * 4;
        const float* src = nx + ((size_t)(b * S_ + st * 64 + r)) * E_ + h * 64 + c4;
        float4 a = *reinterpret_cast<const float4*>(src);
        Xs[r][c4] = a.x; Xs[r][c4 + 1] = a.y; Xs[r][c4 + 2] = a.z; Xs[r][c4 + 3] = a.w;
    }
    const float* Wm[3] = {Wq, Wk, Wv};
    float*       Om[3] = {q, k, v};
    size_t obase = ((size_t)(b * H_ + h) * S_ + st * 64) * D_;
#pragma unroll 1
    for (int m = 0; m < 3; m++) {
        __syncthreads();
#pragma unroll
        for (int it = 0; it < 4; it++) {
            int idx = tid + it * 256;
            int r = idx >> 4, c4 = (idx & 15) * 4;
            float4 a = *reinterpret_cast<const float4*>(Wm[m] + r * 64 + c4);
            Ws[r][c4] = a.x; Ws[r][c4 + 1] = a.y; Ws[r][c4 + 2] = a.z; Ws[r][c4 + 3] = a.w;
        }
        __syncthreads();
        float acc[4][4] = {};
#pragma unroll 4
        for (int d = 0; d < 64; d++) {
            float av[4], bv[4];
#pragma unroll
            for (int i = 0; i < 4; i++) av[i] = Xs[ty * 4 + i][d];
#pragma unroll
            for (int j = 0; j < 4; j++) bv[j] = Ws[d][tx * 4 + j];
#pragma unroll
            for (int i = 0; i < 4; i++)
#pragma unroll
                for (int j = 0; j < 4; j++)
                    acc[i][j] = fmaf(av[i], bv[j], acc[i][j]);
        }
        float* dst = Om[m] + obase;
#pragma unroll
        for (int i = 0; i < 4; i++) {
            float4 o4 = {acc[i][0], acc[i][1], acc[i][2], acc[i][3]};
            *reinterpret_cast<float4*>(dst + (ty * 4 + i) * 64 + tx * 4) = o4;
        }
    }
}

// ---------------- Causal flash attention, 64x64 tiles, mma.tf32 ----------------
// 8 warps as 4(m) x 2(n); warp tile 16x32 for both S=QK^T and O+=P@V.
// Conflict-free fragment strides: Q/K/P 68 (bank=4*r4+c4), V 72 (bank=8*c4+r4).
#define QSTR 68
#define KSTR 68
#define VSTR 72
#define PSTR 68
#define ATTN_SMEM_BYTES ((64 * (QSTR + KSTR + VSTR + PSTR)) * 4)

__global__ __launch_bounds__(256) void attn_kernel(const float* __restrict__ q,
                                                   const float* __restrict__ k,
                                                   const float* __restrict__ v,
                                                   float* __restrict__ o)
{
    extern __shared__ float smem[];
    float* Qs = smem;                  // [64][QSTR]
    float* Ks = Qs + 64 * QSTR;        // [64][KSTR]
    float* Vs = Ks + 64 * KSTR;        // [64][VSTR]
    float* Ps = Vs + 64 * VSTR;        // [64][PSTR]  (S, then P in place)
    __shared__ float m_s[64], l_s[64], corr_s[64];

    int qt = blockIdx.x, h = blockIdx.y, b = blockIdx.z;
    int tid  = threadIdx.x;
    int lane = tid & 31, warp = tid >> 5;
    int wm = warp >> 1, wn = warp & 1;
    int m0 = wm * 16;
    int r4 = lane >> 2, c4 = lane & 3;
    int tx = tid & 15, ty = tid >> 4;
    const float scale = 0.03125f;  // 1/sqrt(E) = 1/32
    size_t head_base = (size_t)(b * H_ + h) * S_ * D_;

    // load Q tile (scaled + tf32)
#pragma unroll
    for (int it = 0; it < 4; it++) {
        int idx = tid + it * 256;
        int r = idx >> 4, c = (idx & 15) * 4;
        float4 a = *reinterpret_cast<const float4*>(q + head_base + (size_t)(qt * 64 + r) * 64 + c);
        float4 o4 = {f2tf32f(a.x * scale), f2tf32f(a.y * scale),
                     f2tf32f(a.z * scale), f2tf32f(a.w * scale)};
        *reinterpret_cast<float4*>(Qs + r * QSTR + c) = o4;
    }
    if (tid < 64) { m_s[tid] = -1e30f; l_s[tid] = 0.f; }

    float acc_o[4][4] = {};

    for (int kt = 0; kt <= qt; kt++) {
        __syncthreads();  // Ks/Vs/Ps safe to overwrite; Qs/m/l initialized (first iter)
#pragma unroll
        for (int it = 0; it < 4; it++) {
            int idx = tid + it * 256;
            int r = idx >> 4, c = (idx & 15) * 4;
            float4 a = *reinterpret_cast<const float4*>(k + head_base + (size_t)(kt * 64 + r) * 64 + c);
            float4 k4 = {f2tf32f(a.x), f2tf32f(a.y), f2tf32f(a.z), f2tf32f(a.w)};
            *reinterpret_cast<float4*>(Ks + r * KSTR + c) = k4;
            float4 bb = *reinterpret_cast<const float4*>(v + head_base + (size_t)(kt * 64 + r) * 64 + c);
            float4 v4 = {f2tf32f(bb.x), f2tf32f(bb.y), f2tf32f(bb.z), f2tf32f(bb.w)};
            *reinterpret_cast<float4*>(Vs + r * VSTR + c) = v4;
        }
        __syncthreads();

        // ---- S = Q @ K^T (warp tile 16x32) ----
        float acc_s[4][4] = {};
#pragma unroll
        for (int ks = 0; ks < 8; ks++) {
            int kc = ks * 8;
            uint32_t a[4];
            a[0] = __float_as_uint(Qs[(m0 + r4) * QSTR + kc + c4]);
            a[1] = __float_as_uint(Qs[(m0 + r4 + 8) * QSTR + kc + c4]);
            a[2] = __float_as_uint(Qs[(m0 + r4) * QSTR + kc + c4 + 4]);
            a[3] = __float_as_uint(Qs[(m0 + r4 + 8) * QSTR + kc + c4 + 4]);
#pragma unroll
            for (int ni = 0; ni < 4; ni++) {
                int n0 = wn * 32 + ni * 8;
                uint32_t bf[2];
                bf[0] = __float_as_uint(Ks[(n0 + r4) * KSTR + kc + c4]);
                bf[1] = __float_as_uint(Ks[(n0 + r4) * KSTR + kc + c4 + 4]);
                mma_tf32(acc_s[ni], a, bf);
            }
        }
        // store S fragments to Ps
#pragma unroll
        for (int ni = 0; ni < 4; ni++) {
            int n0 = wn * 32 + ni * 8 + 2 * c4;
            *reinterpret_cast<float2*>(Ps + (m0 + r4) * PSTR + n0) =
                make_float2(acc_s[ni][0], acc_s[ni][1]);
            *reinterpret_cast<float2*>(Ps + (m0 + r4 + 8) * PSTR + n0) =
                make_float2(acc_s[ni][2], acc_s[ni][3]);
        }
        __syncthreads();

        // ---- online softmax (rows ty*4..+3, cols tx*4..+3) ----
        bool diag = (kt == qt);
#pragma unroll
        for (int i = 0; i < 4; i++) {
            int r = ty * 4 + i;
            float4 s4 = *reinterpret_cast<float4*>(Ps + r * PSTR + tx * 4);
            float sv[4] = {s4.x, s4.y, s4.z, s4.w};
            if (diag) {
#pragma unroll
                for (int j = 0; j < 4; j++)
                    if (tx * 4 + j > r) sv[j] = -1e30f;
            }
            float mm = fmaxf(fmaxf(sv[0], sv[1]), fmaxf(sv[2], sv[3]));
#pragma unroll
            for (int off = 8; off > 0; off >>= 1)
                mm = fmaxf(mm, __shfl_xor_sync(0xffffffffu, mm, off, 16));
            float mo = m_s[r];
            float mn = fmaxf(mo, mm);
            float corr = expf(mo - mn);
            float e0 = expf(sv[0] - mn), e1 = expf(sv[1] - mn);
            float e2 = expf(sv[2] - mn), e3 = expf(sv[3] - mn);
            float rs = e0 + e1 + e2 + e3;
            float4 p4 = {f2tf32f(e0), f2tf32f(e1), f2tf32f(e2), f2tf32f(e3)};
            *reinterpret_cast<float4*>(Ps + r * PSTR + tx * 4) = p4;
#pragma unroll
            for (int off = 8; off > 0; off >>= 1)
                rs += __shfl_xor_sync(0xffffffffu, rs, off, 16);
            if (tx == 0) { m_s[r] = mn; l_s[r] = l_s[r] * corr + rs; corr_s[r] = corr; }
        }
        __syncthreads();

        // ---- O scale + O += P @ V (warp tile 16x32 over d) ----
        float cr0 = corr_s[m0 + r4];
        float cr1 = corr_s[m0 + r4 + 8];
#pragma unroll
        for (int ni = 0; ni < 4; ni++) {
            acc_o[ni][0] *= cr0; acc_o[ni][1] *= cr0;
            acc_o[ni][2] *= cr1; acc_o[ni][3] *= cr1;
        }
#pragma unroll
        for (int ks = 0; ks < 8; ks++) {
            int kc = ks * 8;
            uint32_t a[4];
            a[0] = __float_as_uint(Ps[(m0 + r4) * PSTR + kc + c4]);
            a[1] = __float_as_uint(Ps[(m0 + r4 + 8) * PSTR + kc + c4]);
            a[2] = __float_as_uint(Ps[(m0 + r4) * PSTR + kc + c4 + 4]);
            a[3] = __float_as_uint(Ps[(m0 + r4 + 8) * PSTR + kc + c4 + 4]);
#pragma unroll
            for (int ni = 0; ni < 4; ni++) {
                int n0 = wn * 32 + ni * 8;
                uint32_t bf[2];
                bf[0] = __float_as_uint(Vs[(kc + c4) * VSTR + n0 + r4]);
                bf[1] = __float_as_uint(Vs[(kc + c4 + 4) * VSTR + n0 + r4]);
                mma_tf32(acc_o[ni], a, bf);
            }
        }
    }

    // epilogue: normalize + tf32 round, write token-major [B,S,H,D]
    float inv0 = 1.0f / l_s[m0 + r4];
    float inv1 = 1.0f / l_s[m0 + r4 + 8];
    float* ob = o + ((size_t)(b * S_ + qt * 64)) * E_ + h * 64;
#pragma unroll
    for (int ni = 0; ni < 4; ni++) {
        int cc = wn * 32 + ni * 8 + 2 * c4;
        float2 o0 = {f2tf32f(acc_o[ni][0] * inv0), f2tf32f(acc_o[ni][1] * inv0)};
        float2 o1 = {f2tf32f(acc_o[ni][2] * inv1), f2tf32f(acc_o[ni][3] * inv1)};
        *reinterpret_cast<float2*>(ob + (size_t)(m0 + r4) * E_ + cc)     = o0;
        *reinterpret_cast<float2*>(ob + (size_t)(m0 + r4 + 8) * E_ + cc) = o1;
    }
}

// ---------------- TF32 tensor-core GEMM: 128x128x16 tiles, 3-stage cp.async ----------------
#define BM 128
#define BN 128
#define BK 16
#define ASTRIDE 20        // BK + 4 pad
#define BSTRIDE 136       // BN + 8 pad
#define A_STAGE (BM * ASTRIDE)   // 2560 floats
#define B_STAGE (BK * BSTRIDE)   // 2176 floats
#define GEMM_SMEM_BYTES ((3 * A_STAGE + 3 * B_STAGE) * 4)  // 56832

template <int RELU, int RES, int TF32OUT>
__global__ __launch_bounds__(256) void tgemm_kernel(const float* __restrict__ A,
                                                    const float* __restrict__ Bm,
                                                    const float* __restrict__ bias,
                                                    const float* __restrict__ resid,
                                                    float* __restrict__ C,
                                                    int M, int N, int K)
{
    extern __shared__ float sh[];
    float* Asm = sh;                   // [3][BM][ASTRIDE]
    float* Bsm = sh + 3 * A_STAGE;     // [3][BK][BSTRIDE]

    const int tid  = threadIdx.x;
    const int lane = tid & 31;
    const int warp = tid >> 5;
    const int wm = warp >> 2;          // 0..1
    const int wn = warp & 3;           // 0..3
    const int m_w = wm * 64;
    const int n_w = wn * 32;
    const int r4 = lane >> 2;          // 0..7
    const int c4 = lane & 3;           // 0..3
    const int bx = blockIdx.x, by = blockIdx.y;

    const float* Ab = A + (size_t)by * BM * K;
    const float* Bb = Bm + (size_t)bx * BN;

    auto load_tile = [&](int buf, int k0) {
        float* Ad = Asm + buf * A_STAGE;
        float* Bd = Bsm + buf * B_STAGE;
#pragma unroll
        for (int i = 0; i < 2; i++) {
            int idx = tid + i * 256;
            int row = idx >> 2, kq = (idx & 3) * 4;
            cp_async16(Ad + row * ASTRIDE + kq, Ab + (size_t)row * K + k0 + kq);
        }
#pragma unroll
        for (int i = 0; i < 2; i++) {
            int idx = tid + i * 256;
            int row = idx >> 5, nq = (idx & 31) * 4;
            cp_async16(Bd + row * BSTRIDE + nq, Bb + (size_t)(k0 + row) * N + nq);
        }
        CP_COMMIT();
    };

    float acc[4][4][4] = {};

    const int nT = K / BK;
    load_tile(0, 0);
    load_tile(1, BK);

#pragma unroll 1
    for (int t = 0; t < nT; t++) {
        if (t + 1 < nT) { CP_WAIT1(); } else { CP_WAIT0(); }
        __syncthreads();
        if (t + 2 < nT) load_tile((t + 2) % 3, (t + 2) * BK);

        const float* Ac = Asm + (t % 3) * A_STAGE;
        const float* Bc = Bsm + (t % 3) * B_STAGE;
#pragma unroll
        for (int ks = 0; ks < 2; ks++) {
            const int kc = ks * 8;
            uint32_t a[4][4], b[4][2];
#pragma unroll
            for (int mi = 0; mi < 4; mi++) {
                int m0 = m_w + mi * 16;
                a[mi][0] = __float_as_uint(Ac[(m0 + r4) * ASTRIDE + kc + c4]);
                a[mi][1] = __float_as_uint(Ac[(m0 + r4 + 8) * ASTRIDE + kc + c4]);
                a[mi][2] = __float_as_uint(Ac[(m0 + r4) * ASTRIDE + kc + c4 + 4]);
                a[mi][3] = __float_as_uint(Ac[(m0 + r4 + 8) * ASTRIDE + kc + c4 + 4]);
            }
#pragma unroll
            for (int ni = 0; ni < 4; ni++) {
                int n0 = n_w + ni * 8;
                b[ni][0] = __float_as_uint(Bc[(kc + c4) * BSTRIDE + n0 + r4]);
                b[ni][1] = __float_as_uint(Bc[(kc + c4 + 4) * BSTRIDE + n0 + r4]);
            }
#pragma unroll
            for (int mi = 0; mi < 4; mi++)
#pragma unroll
                for (int ni = 0; ni < 4; ni++)
                    mma_tf32(acc[mi][ni], a[mi], b[ni]);
        }
        // no trailing sync: leading sync next iter orders buffer reuse
    }

    // epilogue
    const int row_base = by * BM + m_w;
    const int col_base = bx * BN + n_w;
#pragma unroll
    for (int mi = 0; mi < 4; mi++) {
#pragma unroll
        for (int ni = 0; ni < 4; ni++) {
            int c0 = col_base + ni * 8 + 2 * c4;
            float2 bb = *reinterpret_cast<const float2*>(bias + c0);
#pragma unroll
            for (int half = 0; half < 2; half++) {
                int r0 = row_base + mi * 16 + r4 + half * 8;
                float v0 = acc[mi][ni][half * 2]     + bb.x;
                float v1 = acc[mi][ni][half * 2 + 1] + bb.y;
                if (RELU) { v0 = fmaxf(v0, 0.f); v1 = fmaxf(v1, 0.f); }
                if (RES) {
                    float2 rr = *reinterpret_cast<const float2*>(resid + (size_t)r0 * N + c0);
                    v0 += rr.x; v1 += rr.y;
                }
                if (TF32OUT) { v0 = f2tf32f(v0); v1 = f2tf32f(v1); }
                float2 o2 = {v0, v1};
                *reinterpret_cast<float2*>(C + (size_t)r0 * N + c0) = o2;
            }
        }
    }
}

// ---------------- launch ----------------
extern "C" void kernel_launch(void* const* d_in, const int* in_sizes, int n_in,
                              void* d_out, int out_size)
{
    (void)in_sizes; (void)n_in; (void)out_size;
    const float* x   = (const float*)d_in[0];
    const float* Wq  = (const float*)d_in[1];
    const float* Wk  = (const float*)d_in[2];
    const float* Wv  = (const float*)d_in[3];
    const float* Wo  = (const float*)d_in[4];
    const float* bo  = (const float*)d_in[5];
    const float* W1  = (const float*)d_in[6];
    const float* b1  = (const float*)d_in[7];
    const float* W2  = (const float*)d_in[8];
    const float* b2  = (const float*)d_in[9];
    const float* g1  = (const float*)d_in[10];
    const float* be1 = (const float*)d_in[11];
    const float* g2  = (const float*)d_in[12];
    const float* be2 = (const float*)d_in[13];
    float* out = (float*)d_out;

    float *nx, *qb, *kb, *vb, *ob, *x1, *nx2, *h1, *wo, *w1, *w2;
    cudaGetSymbolAddress((void**)&nx,  g_nx);
    cudaGetSymbolAddress((void**)&qb,  g_q);
    cudaGetSymbolAddress((void**)&kb,  g_k);
    cudaGetSymbolAddress((void**)&vb,  g_v);
    cudaGetSymbolAddress((void**)&ob,  g_o);
    cudaGetSymbolAddress((void**)&x1,  g_x1);
    cudaGetSymbolAddress((void**)&nx2, g_nx2);
    cudaGetSymbolAddress((void**)&h1,  g_h1);
    cudaGetSymbolAddress((void**)&wo,  g_wo);
    cudaGetSymbolAddress((void**)&w1,  g_w1);
    cudaGetSymbolAddress((void**)&w2,  g_w2);

    cudaFuncSetAttribute(attn_kernel, cudaFuncAttributeMaxDynamicSharedMemorySize,
                         ATTN_SMEM_BYTES);
    cudaFuncSetAttribute(tgemm_kernel<0, 1, 0>, cudaFuncAttributeMaxDynamicSharedMemorySize,
                         GEMM_SMEM_BYTES);
    cudaFuncSetAttribute(tgemm_kernel<1, 0, 1>, cudaFuncAttributeMaxDynamicSharedMemorySize,
                         GEMM_SMEM_BYTES);

    // 0) pre-round weights to tf32
    cvt_tf32_kernel<<<(E_ * E_ / 4 + 255) / 256, 256>>>(Wo, wo, E_ * E_ / 4);
    cvt_tf32_kernel<<<(E_ * F_ / 4 + 255) / 256, 256>>>(W1, w1, E_ * F_ / 4);
    cvt_tf32_kernel<<<(F_ * E_ / 4 + 255) / 256, 256>>>(W2, w2, F_ * E_ / 4);
    // 1) LN1
    ln_kernel<0><<<TOK, 256>>>(x, g1, be1, nx);
    // 2) QKV projections
    qkv_kernel<<<dim3(S_ / 64, H_, B_), 256>>>(nx, Wq, Wk, Wv, qb, kb, vb);
    // 3) causal flash attention (tensor cores) -> o (token-major, tf32-rounded)
    attn_kernel<<<dim3(S_ / 64, H_, B_), 256, ATTN_SMEM_BYTES>>>(qb, kb, vb, ob);
    // 4) x1 = x + o @ Wo + bo
    tgemm_kernel<0, 1, 0><<<dim3(E_ / BN, TOK / BM), 256, GEMM_SMEM_BYTES>>>(ob, wo, bo, x, x1, TOK, E_, E_);
    // 5) LN2 (tf32-rounded out)
    ln_kernel<1><<<TOK, 256>>>(x1, g2, be2, nx2);
    // 6) h1 = relu(nx2 @ W1 + b1), tf32-rounded out
    tgemm_kernel<1, 0, 1><<<dim3(F_ / BN, TOK / BM), 256, GEMM_SMEM_BYTES>>>(nx2, w1, b1, nullptr, h1, TOK, F_, E_);
    // 7) out = x1 + h1 @ W2 + b2
    tgemm_kernel<0, 1, 0><<<dim3(E_ / BN, TOK / BM), 256, GEMM_SMEM_BYTES>>>(h1, w2, b2, x1, out, TOK, E_, F_);
}